// round 16
// baseline (speedup 1.0000x reference)
#include <cuda_runtime.h>
#include <cuda_fp16.h>
#include <math.h>
#include <stdint.h>

// Problem constants
#define NN     50000
#define DH     128
#define S_NEI  25
#define MT     64                      // rows per CTA tile
#define NTILES ((NN + MT - 1) / MT)    // 782

// ---------------- scratch (device globals; no allocation allowed) -----------
__device__ __align__(16) __half g_h1 [(size_t)NN * DH];   // fp16 gather table L1
__device__ __align__(16) __half g_f16[(size_t)NN * DH];   // fp16 features
__device__ __align__(16) __half g_x1 [(size_t)NN * DH];   // pre-BN activations
__device__ __align__(16) __half g_xn [(size_t)NN * DH];   // post-BN row-normed
__device__ __align__(16) __half g_h2 [(size_t)NN * DH];   // fp16 gather table L2
__device__ float g_sum[DH];
__device__ float g_sq[DH];
// fragment-packed fp16 weights:
// block (kb, cg) = 8 cols x 16 k, 32 lanes x uint2; index ((kb*16+cg)*32+lane)
__device__ __align__(16) uint2 g_w1p [ 8 * 16 * 32];   // K=128
__device__ __align__(16) uint2 g_wf1p[16 * 16 * 32];   // K=256
__device__ __align__(16) uint2 g_w2p [ 8 * 16 * 32];   // K=128
__device__ __align__(16) uint2 g_wf2p[16 * 16 * 32];   // K=256

// ---------------- pack one 16-row K-block of a [K x 128] fp32 matrix ---------
__device__ __forceinline__ void pack_mat(const float* __restrict__ src,
                                         uint2* __restrict__ dst, int kb) {
#pragma unroll
    for (int s = 0; s < 2; ++s) {
        int e    = threadIdx.x + s * 256;          // 0..511 = (cg, lane)
        int cg   = e >> 5, lane = e & 31;
        int col  = cg * 8 + (lane >> 2);
        int tig  = lane & 3;
        int k0   = kb * 16 + 2 * tig;
        __half2 p0 = __floats2half2_rn(src[(k0    ) * DH + col],
                                       src[(k0 + 1) * DH + col]);
        __half2 p1 = __floats2half2_rn(src[(k0 + 8) * DH + col],
                                       src[(k0 + 9) * DH + col]);
        uint2 o;
        o.x = *(uint32_t*)&p0;
        o.y = *(uint32_t*)&p1;
        dst[(kb * 16 + cg) * 32 + lane] = o;
    }
}

// ---------------- prep1: pack w1p (needed by K1) + zero BN stats -------------
__global__ void prep1_kernel(const float* __restrict__ w1,
                             float* gsum, float* gsq) {
    if (blockIdx.x == 0 && threadIdx.x < DH) {
        gsum[threadIdx.x] = 0.f;
        gsq[threadIdx.x]  = 0.f;
    }
    pack_mat(w1, g_w1p, blockIdx.x);   // 8 blocks
}

// ---------------- fp16 MMA ----------------------------------------------------
__device__ __forceinline__ void mma_f16(float* c, const uint32_t* a,
                                        const uint32_t* b) {
    asm volatile(
        "mma.sync.aligned.m16n8k16.row.col.f32.f16.f16.f32 "
        "{%0,%1,%2,%3}, {%4,%5,%6,%7}, {%8,%9}, {%0,%1,%2,%3};\n"
        : "+f"(c[0]), "+f"(c[1]), "+f"(c[2]), "+f"(c[3])
        : "r"(a[0]), "r"(a[1]), "r"(a[2]), "r"(a[3]), "r"(b[0]), "r"(b[1]));
}

__device__ __forceinline__ void store2(float* p, float x0, float x1) {
    *(float2*)p = make_float2(x0, x1);
}
__device__ __forceinline__ void store2(__half* p, float x0, float x1) {
    *(__half2*)p = __floats2half2_rn(x0, x1);
}

// ---------------- barrier-free fp16 GEMM core ---------------------------------
// MT(64) x DH(128) tile: acc[mi 2][ni 4][4]; 8 warps = 2(M) x 4(N).
// As: fp16, row stride KPADH = KDIM+8 (conflict-free frags).
// B fragments loaded straight from packed weights (L1/L2-resident, coalesced).
// Exactly ONE __syncthreads (publishes As); warps run free afterwards.
template<int KDIM>
__device__ __forceinline__ void gemm_f16(const __half* __restrict__ As,
                                         const uint2* __restrict__ Wp,
                                         int tid, float acc[2][4][4])
{
    constexpr int KPADH = KDIM + 8;
    constexpr int NKB   = KDIM / 16;
    const int gid = (tid & 31) >> 2, tig = tid & 3;
    const int wm  = (tid >> 5) >> 2, wn  = (tid >> 5) & 3;
    const uint2* wbase = Wp + (wn * 4) * 32 + (tid & 31);

    __syncthreads();   // publishes As

#pragma unroll 4
    for (int kb = 0; kb < NKB; ++kb) {
        uint2 bv[4];
#pragma unroll
        for (int ni = 0; ni < 4; ++ni)
            bv[ni] = __ldg(wbase + kb * 512 + ni * 32);

        uint32_t a[2][4];
#pragma unroll
        for (int mi = 0; mi < 2; ++mi) {
            const __half* ap = As + (wm * 32 + mi * 16 + gid) * KPADH
                                  + kb * 16 + 2 * tig;
            a[mi][0] = *(const uint32_t*)ap;
            a[mi][1] = *(const uint32_t*)(ap + 8 * KPADH);
            a[mi][2] = *(const uint32_t*)(ap + 8);
            a[mi][3] = *(const uint32_t*)(ap + 8 * KPADH + 8);
        }
#pragma unroll
        for (int mi = 0; mi < 2; ++mi)
#pragma unroll
            for (int ni = 0; ni < 4; ++ni)
                mma_f16(acc[mi][ni], a[mi], (const uint32_t*)&bv[ni]);
    }
}

// ---------------- fused layer kernel ------------------------------------------
// GATHER=false, KDIM=128 : out = act(X @ W + b)
// GATHER=true,  KDIM=256 : out = act([X | max_j Htab16[idx[r][j]]] @ W + b)
// STATS : accumulate per-column sum / sumsq of the activation.
// PACKT : blocks >= NTILES pack the remaining weight matrices (wf1p/w2p/wf2p)
//         concurrently with the tile blocks (K1 only).
// MINB  : min blocks per SM (register budget: 4 needs <=64 regs)
template<int KDIM, bool RELU, bool GATHER, bool STATS, bool PACKT,
         bool FEAT16, bool WRITEF16, typename OUTT, int MINB>
__global__ void __launch_bounds__(256, MINB)
layer_kernel(const float*  __restrict__ Xf,     // fp32 features (FEAT16=false)
             const __half* __restrict__ Xh,     // fp16 features (FEAT16=true)
             const __half* __restrict__ Htab,
             const int*    __restrict__ nidx,
             const uint2*  __restrict__ Wp,
             const float*  __restrict__ bias,
             OUTT*   __restrict__ out,
             __half* __restrict__ f16out,
             float*  __restrict__ gsum,
             float*  __restrict__ gsq,
             const float* __restrict__ pf1,     // PACKT: fc1_W
             const float* __restrict__ pw2,     // PACKT: agg2_W
             const float* __restrict__ pf2)     // PACKT: fc2_W
{
    if (PACKT && blockIdx.x >= NTILES) {
        int b = blockIdx.x - NTILES;             // 0..39
        if      (b < 16) pack_mat(pf1, g_wf1p, b);
        else if (b < 24) pack_mat(pw2, g_w2p,  b - 16);
        else             pack_mat(pf2, g_wf2p, b - 24);
        return;
    }

    extern __shared__ __half sm[];
    constexpr int KPADH = KDIM + 8;
    __half* As  = sm;                             // MT * KPADH halfs
    float*  Sst = (float*)(sm + MT * KPADH);      // 256 floats (STATS)

    const int tid  = threadIdx.x;
    const int lane = tid & 31, wrp = tid >> 5;
    const int gid  = lane >> 2, tig = lane & 3;
    const int wm   = wrp >> 2,  wn  = wrp & 3;
    const int m0   = blockIdx.x * MT;

    if (STATS) Sst[tid] = 0.f;

    // ---- Phase A: stage A tile (features + optional fp16 gather-max) ----
#pragma unroll
    for (int q = 0; q < MT / 8; ++q) {
        int lr = wrp * (MT / 8) + q;
        int r  = m0 + lr; if (r >= NN) r = NN - 1;   // clamp (dup rows benign)

        if (FEAT16) {
            uint2 v = *(const uint2*)(Xh + (size_t)r * DH + lane * 4);
            *(uint2*)(As + lr * KPADH + lane * 4) = v;
        } else {
            float4 f = *(const float4*)(Xf + (size_t)r * DH + lane * 4);
            __half2 h0 = __floats2half2_rn(f.x, f.y);
            __half2 h1 = __floats2half2_rn(f.z, f.w);
            uint2 v;
            v.x = *(uint32_t*)&h0; v.y = *(uint32_t*)&h1;
            *(uint2*)(As + lr * KPADH + lane * 4) = v;
            if (WRITEF16)
                *(uint2*)(f16out + (size_t)r * DH + lane * 4) = v;
        }

        if (GATHER) {
            // half-warp scheme: lanes 0-15 take neighbors 0..12,
            // lanes 16-31 take 12..24 (j=12 duplicated; max idempotent).
            const int c  = lane & 15, hw = lane >> 4;
            const int* nb = nidx + r * S_NEI + hw * 12;
            __half2 mx0 = __float2half2_rn(0.f);   // post-relu values >= 0
            __half2 mx1 = mx0, mx2 = mx0, mx3 = mx0;
#pragma unroll
            for (int t = 0; t < 13; ++t) {
                int id = __ldg(nb + t);
                uint4 v = *(const uint4*)(Htab + (size_t)id * DH + c * 8);
                mx0 = __hmax2(mx0, *(__half2*)&v.x);
                mx1 = __hmax2(mx1, *(__half2*)&v.y);
                mx2 = __hmax2(mx2, *(__half2*)&v.z);
                mx3 = __hmax2(mx3, *(__half2*)&v.w);
            }
            uint4 o;
            uint32_t* mo = (uint32_t*)&o;
            __half2 mx[4] = {mx0, mx1, mx2, mx3};
#pragma unroll
            for (int i = 0; i < 4; ++i) {
                uint32_t mm = *(uint32_t*)&mx[i];
                uint32_t ot = __shfl_xor_sync(0xffffffffu, mm, 16);
                __half2 rr  = __hmax2(*(__half2*)&mm, *(__half2*)&ot);
                mo[i] = *(uint32_t*)&rr;
            }
            if (hw == 0)
                *(uint4*)(As + lr * KPADH + DH + c * 8) = o;
        }
    }

    float2 bb[4];
#pragma unroll
    for (int ni = 0; ni < 4; ++ni)
        bb[ni] = *(const float2*)(bias + wn * 32 + ni * 8 + 2 * tig);

    float acc[2][4][4];
#pragma unroll
    for (int mi = 0; mi < 2; ++mi)
#pragma unroll
        for (int ni = 0; ni < 4; ++ni)
#pragma unroll
            for (int c = 0; c < 4; ++c) acc[mi][ni][c] = 0.f;

    gemm_f16<KDIM>(As, Wp, tid, acc);

    // ---- Epilogue ----
    float ps[8], pq[8];
    if (STATS) {
#pragma unroll
        for (int j = 0; j < 8; ++j) { ps[j] = 0.f; pq[j] = 0.f; }
    }
#pragma unroll
    for (int mi = 0; mi < 2; ++mi) {
#pragma unroll
        for (int h = 0; h < 2; ++h) {
            int r = m0 + wm * 32 + mi * 16 + h * 8 + gid;
            if (r < NN) {
#pragma unroll
                for (int ni = 0; ni < 4; ++ni) {
                    float x0 = acc[mi][ni][h * 2 + 0] + bb[ni].x;
                    float x1 = acc[mi][ni][h * 2 + 1] + bb[ni].y;
                    if (RELU) { x0 = fmaxf(x0, 0.f); x1 = fmaxf(x1, 0.f); }
                    if (STATS) {
                        ps[ni * 2]     += x0; pq[ni * 2]     += x0 * x0;
                        ps[ni * 2 + 1] += x1; pq[ni * 2 + 1] += x1 * x1;
                    }
                    store2(out + (size_t)r * DH + wn * 32 + ni * 8 + 2 * tig,
                           x0, x1);
                }
            }
        }
    }

    if (STATS) {
        // reduce over gid (lanes 4 apart share tig)
#pragma unroll
        for (int j = 0; j < 8; ++j) {
#pragma unroll
            for (int o = 16; o >= 4; o >>= 1) {
                ps[j] += __shfl_xor_sync(0xffffffffu, ps[j], o);
                pq[j] += __shfl_xor_sync(0xffffffffu, pq[j], o);
            }
        }
        if (gid == 0) {
#pragma unroll
            for (int ni = 0; ni < 4; ++ni) {
                int c = wn * 32 + ni * 8 + 2 * tig;
                atomicAdd(Sst + c,           ps[ni * 2]);
                atomicAdd(Sst + c + 1,       ps[ni * 2 + 1]);
                atomicAdd(Sst + 128 + c,     pq[ni * 2]);
                atomicAdd(Sst + 128 + c + 1, pq[ni * 2 + 1]);
            }
        }
        __syncthreads();
        if (tid < DH) {
            atomicAdd(gsum + tid, Sst[tid]);
            atomicAdd(gsq + tid,  Sst[128 + tid]);
        }
    }
}

// ---------------- BN(inline finalize) + row-norm + GEMM -----------------------
__global__ void __launch_bounds__(256, 4)
bn_rownorm_gemm_kernel(const __half* __restrict__ X1,
                       const float* __restrict__ gsum,
                       const float* __restrict__ gsq,
                       const float* __restrict__ gamma,
                       const float* __restrict__ beta,
                       const uint2* __restrict__ Wp,
                       const float* __restrict__ bias,
                       __half* __restrict__ xn,
                       __half* __restrict__ h2)
{
    extern __shared__ __half sm[];
    constexpr int KPADH = DH + 8;
    __half* As = sm;

    const int tid  = threadIdx.x;
    const int lane = tid & 31, wrp = tid >> 5;
    const int gid  = lane >> 2, tig = tid & 3;
    const int wm   = wrp >> 2,  wn  = wrp & 3;
    const int m0   = blockIdx.x * MT;

    // inline BN finalize for this lane's 4 channels
    float sc[4], sh[4];
    {
        const float invN = 1.f / (float)NN;
#pragma unroll
        for (int i = 0; i < 4; ++i) {
            int c = lane * 4 + i;
            float mean = __ldg(gsum + c) * invN;
            float var  = __ldg(gsq + c) * invN - mean * mean;
            float s    = rsqrtf(var + 1e-5f) * __ldg(gamma + c);
            sc[i] = s;
            sh[i] = __ldg(beta + c) - mean * s;
        }
    }

    // batched row loads: all 8 LDGs in flight before any processing (MLP=8)
    uint2 raw[MT / 8];
#pragma unroll
    for (int q = 0; q < MT / 8; ++q) {
        int r = m0 + wrp * (MT / 8) + q; if (r >= NN) r = NN - 1;
        raw[q] = *(const uint2*)(X1 + (size_t)r * DH + lane * 4);
    }

#pragma unroll
    for (int q = 0; q < MT / 8; ++q) {
        int lr = wrp * (MT / 8) + q;
        int r  = m0 + lr; if (r >= NN) r = NN - 1;
        float2 f0 = __half22float2(*(__half2*)&raw[q].x);
        float2 f1 = __half22float2(*(__half2*)&raw[q].y);
        float v0 = fmaf(f0.x, sc[0], sh[0]);
        float v1 = fmaf(f0.y, sc[1], sh[1]);
        float v2 = fmaf(f1.x, sc[2], sh[2]);
        float v3 = fmaf(f1.y, sc[3], sh[3]);
        float ss = v0 * v0 + v1 * v1 + v2 * v2 + v3 * v3;
#pragma unroll
        for (int o = 16; o; o >>= 1) ss += __shfl_xor_sync(0xffffffffu, ss, o);
        float inv = 1.f / (sqrtf(ss) + 1e-6f);
        v0 *= inv; v1 *= inv; v2 *= inv; v3 *= inv;
        __half2 h0 = __floats2half2_rn(v0, v1);
        __half2 h1 = __floats2half2_rn(v2, v3);
        uint2 v;
        v.x = *(uint32_t*)&h0; v.y = *(uint32_t*)&h1;
        *(uint2*)(As + lr * KPADH + lane * 4) = v;
        *(uint2*)(xn + (size_t)r * DH + lane * 4) = v;  // dup rows same value
    }

    float2 bb[4];
#pragma unroll
    for (int ni = 0; ni < 4; ++ni)
        bb[ni] = *(const float2*)(bias + wn * 32 + ni * 8 + 2 * tig);

    float acc[2][4][4];
#pragma unroll
    for (int mi = 0; mi < 2; ++mi)
#pragma unroll
        for (int ni = 0; ni < 4; ++ni)
#pragma unroll
            for (int c = 0; c < 4; ++c) acc[mi][ni][c] = 0.f;

    gemm_f16<DH>(As, Wp, tid, acc);

#pragma unroll
    for (int mi = 0; mi < 2; ++mi) {
#pragma unroll
        for (int h = 0; h < 2; ++h) {
            int r = m0 + wm * 32 + mi * 16 + h * 8 + gid;
            if (r < NN) {
#pragma unroll
                for (int ni = 0; ni < 4; ++ni) {
                    float x0 = fmaxf(acc[mi][ni][h * 2 + 0] + bb[ni].x, 0.f);
                    float x1 = fmaxf(acc[mi][ni][h * 2 + 1] + bb[ni].y, 0.f);
                    store2(h2 + (size_t)r * DH + wn * 32 + ni * 8 + 2 * tig,
                           x0, x1);
                }
            }
        }
    }
}

// ---------------- host launch --------------------------------------------------
extern "C" void kernel_launch(void* const* d_in, const int* in_sizes, int n_in,
                              void* d_out, int out_size)
{
    const float* features = (const float*)d_in[0];
    const int*   idx1     = (const int*)  d_in[1];
    const int*   idx2     = (const int*)  d_in[2];
    const float* agg1_W   = (const float*)d_in[3];
    const float* agg1_b   = (const float*)d_in[4];
    const float* fc1_W    = (const float*)d_in[5];
    const float* fc1_b    = (const float*)d_in[6];
    const float* agg2_W   = (const float*)d_in[7];
    const float* agg2_b   = (const float*)d_in[8];
    const float* fc2_W    = (const float*)d_in[9];
    const float* fc2_b    = (const float*)d_in[10];
    const float* gamma    = (const float*)d_in[11];
    const float* beta     = (const float*)d_in[12];
    float* out = (float*)d_out;

    void *h1, *f16, *x1, *xn, *h2, *gsum, *gsq;
    void *w1p, *wf1p, *w2p, *wf2p;
    cudaGetSymbolAddress(&h1,   g_h1);
    cudaGetSymbolAddress(&f16,  g_f16);
    cudaGetSymbolAddress(&x1,   g_x1);
    cudaGetSymbolAddress(&xn,   g_xn);
    cudaGetSymbolAddress(&h2,   g_h2);
    cudaGetSymbolAddress(&gsum, g_sum);
    cudaGetSymbolAddress(&gsq,  g_sq);
    cudaGetSymbolAddress(&w1p,  g_w1p);
    cudaGetSymbolAddress(&wf1p, g_wf1p);
    cudaGetSymbolAddress(&w2p,  g_w2p);
    cudaGetSymbolAddress(&wf2p, g_wf2p);

    const int sm128  = MT * (128 + 8) * 2;                 // 17408 B
    const int sm256  = MT * (256 + 8) * 2;                 // 33792 B
    const int sm256s = sm256 + 256 * (int)sizeof(float);   // 34816 B

    cudaFuncSetAttribute(
        (const void*)layer_kernel<128, true, false, false, true, false, true, __half, 4>,
        cudaFuncAttributeMaxDynamicSharedMemorySize, sm128);
    cudaFuncSetAttribute(
        (const void*)layer_kernel<256, true, true, true, false, true, false, __half, 3>,
        cudaFuncAttributeMaxDynamicSharedMemorySize, sm256s);
    cudaFuncSetAttribute(
        (const void*)layer_kernel<256, false, true, false, false, true, false, float, 4>,
        cudaFuncAttributeMaxDynamicSharedMemorySize, sm256);
    cudaFuncSetAttribute((const void*)bn_rownorm_gemm_kernel,
        cudaFuncAttributeMaxDynamicSharedMemorySize, sm128);

    // K0: pack w1p (needed by K1) + zero BN stats — tiny (8 blocks)
    prep1_kernel<<<8, 256>>>(agg1_W, (float*)gsum, (float*)gsq);

    // K1: h1 = relu(F @ W1 + b) -> fp16; emits fp16 features.
    //     Extra 40 blocks pack wf1p/w2p/wf2p concurrently (ready before K2).
    layer_kernel<128, true, false, false, true, false, true, __half, 4>
        <<<NTILES + 40, 256, sm128>>>(
        features, nullptr, nullptr, nullptr, (const uint2*)w1p, agg1_b,
        (__half*)h1, (__half*)f16, (float*)gsum, (float*)gsq,
        fc1_W, agg2_W, fc2_W);

    // K2: x1 = relu([F16 | max h1[idx1]] @ Wf1 + b) -> fp16; BN stats
    layer_kernel<256, true, true, true, false, true, false, __half, 3>
        <<<NTILES, 256, sm256s>>>(
        nullptr, (const __half*)f16, (const __half*)h1, idx1,
        (const uint2*)wf1p, fc1_b, (__half*)x1, nullptr,
        (float*)gsum, (float*)gsq, nullptr, nullptr, nullptr);

    // K3: xn = rownorm(BN(x1)) -> fp16; h2 = relu(xn @ W2 + b) -> fp16
    bn_rownorm_gemm_kernel<<<NTILES, 256, sm128>>>(
        (const __half*)x1, (const float*)gsum, (const float*)gsq, gamma, beta,
        (const uint2*)w2p, agg2_b, (__half*)xn, (__half*)h2);

    // K4: out = [xn | max h2[idx2]] @ Wf2 + b  (fp32 output), occ 4
    layer_kernel<256, false, true, false, false, true, false, float, 4>
        <<<NTILES, 256, sm256>>>(
        nullptr, (const __half*)xn, (const __half*)h2, idx2,
        (const uint2*)wf2p, fc2_b, out, nullptr, nullptr, nullptr,
        nullptr, nullptr, nullptr);
}

// round 17
// speedup vs baseline: 1.0562x; 1.0562x over previous
#include <cuda_runtime.h>
#include <cuda_fp16.h>
#include <math.h>
#include <stdint.h>

// Problem constants
#define NN     50000
#define DH     128
#define S_NEI  25
#define MT     64                      // rows per CTA tile
#define NTILES ((NN + MT - 1) / MT)    // 782

// ---------------- scratch (device globals; no allocation allowed) -----------
__device__ __align__(16) __half g_h1 [(size_t)NN * DH];   // fp16 gather table L1
__device__ __align__(16) __half g_f16[(size_t)NN * DH];   // fp16 features
__device__ __align__(16) __half g_x1 [(size_t)NN * DH];   // pre-BN activations
__device__ __align__(16) __half g_xn [(size_t)NN * DH];   // post-BN row-normed
__device__ __align__(16) __half g_h2 [(size_t)NN * DH];   // fp16 gather table L2
__device__ float g_sum[DH];
__device__ float g_sq[DH];
// fragment-packed fp16 weights:
// block (kb, cg) = 8 cols x 16 k, 32 lanes x uint2; index ((kb*16+cg)*32+lane)
__device__ __align__(16) uint2 g_w1p [ 8 * 16 * 32];   // K=128
__device__ __align__(16) uint2 g_wf1p[16 * 16 * 32];   // K=256
__device__ __align__(16) uint2 g_w2p [ 8 * 16 * 32];   // K=128
__device__ __align__(16) uint2 g_wf2p[16 * 16 * 32];   // K=256

// ---------------- pack one 16-row K-block of a [K x 128] fp32 matrix ---------
__device__ __forceinline__ void pack_mat(const float* __restrict__ src,
                                         uint2* __restrict__ dst, int kb) {
#pragma unroll
    for (int s = 0; s < 2; ++s) {
        int e    = threadIdx.x + s * 256;          // 0..511 = (cg, lane)
        int cg   = e >> 5, lane = e & 31;
        int col  = cg * 8 + (lane >> 2);
        int tig  = lane & 3;
        int k0   = kb * 16 + 2 * tig;
        __half2 p0 = __floats2half2_rn(src[(k0    ) * DH + col],
                                       src[(k0 + 1) * DH + col]);
        __half2 p1 = __floats2half2_rn(src[(k0 + 8) * DH + col],
                                       src[(k0 + 9) * DH + col]);
        uint2 o;
        o.x = *(uint32_t*)&p0;
        o.y = *(uint32_t*)&p1;
        dst[(kb * 16 + cg) * 32 + lane] = o;
    }
}

// ---------------- prep1: pack w1p (needed by K1) + zero BN stats -------------
__global__ void prep1_kernel(const float* __restrict__ w1,
                             float* gsum, float* gsq) {
    if (blockIdx.x == 0 && threadIdx.x < DH) {
        gsum[threadIdx.x] = 0.f;
        gsq[threadIdx.x]  = 0.f;
    }
    pack_mat(w1, g_w1p, blockIdx.x);   // 8 blocks
}

// ---------------- fp16 MMA ----------------------------------------------------
__device__ __forceinline__ void mma_f16(float* c, const uint32_t* a,
                                        const uint32_t* b) {
    asm volatile(
        "mma.sync.aligned.m16n8k16.row.col.f32.f16.f16.f32 "
        "{%0,%1,%2,%3}, {%4,%5,%6,%7}, {%8,%9}, {%0,%1,%2,%3};\n"
        : "+f"(c[0]), "+f"(c[1]), "+f"(c[2]), "+f"(c[3])
        : "r"(a[0]), "r"(a[1]), "r"(a[2]), "r"(a[3]), "r"(b[0]), "r"(b[1]));
}

__device__ __forceinline__ void store2(float* p, float x0, float x1) {
    *(float2*)p = make_float2(x0, x1);
}
__device__ __forceinline__ void store2(__half* p, float x0, float x1) {
    *(__half2*)p = __floats2half2_rn(x0, x1);
}

// ---------------- barrier-free fp16 GEMM core ---------------------------------
// MT(64) x DH(128) tile: acc[mi 2][ni 4][4]; 8 warps = 2(M) x 4(N).
// As: fp16, row stride KPADH = KDIM+8 (conflict-free frags).
// B fragments loaded straight from packed weights (L1/L2-resident, coalesced).
// Exactly ONE __syncthreads (publishes As); warps run free afterwards.
template<int KDIM>
__device__ __forceinline__ void gemm_f16(const __half* __restrict__ As,
                                         const uint2* __restrict__ Wp,
                                         int tid, float acc[2][4][4])
{
    constexpr int KPADH = KDIM + 8;
    constexpr int NKB   = KDIM / 16;
    const int gid = (tid & 31) >> 2, tig = tid & 3;
    const int wm  = (tid >> 5) >> 2, wn  = (tid >> 5) & 3;
    const uint2* wbase = Wp + (wn * 4) * 32 + (tid & 31);

    __syncthreads();   // publishes As

#pragma unroll 4
    for (int kb = 0; kb < NKB; ++kb) {
        uint2 bv[4];
#pragma unroll
        for (int ni = 0; ni < 4; ++ni)
            bv[ni] = __ldg(wbase + kb * 512 + ni * 32);

        uint32_t a[2][4];
#pragma unroll
        for (int mi = 0; mi < 2; ++mi) {
            const __half* ap = As + (wm * 32 + mi * 16 + gid) * KPADH
                                  + kb * 16 + 2 * tig;
            a[mi][0] = *(const uint32_t*)ap;
            a[mi][1] = *(const uint32_t*)(ap + 8 * KPADH);
            a[mi][2] = *(const uint32_t*)(ap + 8);
            a[mi][3] = *(const uint32_t*)(ap + 8 * KPADH + 8);
        }
#pragma unroll
        for (int mi = 0; mi < 2; ++mi)
#pragma unroll
            for (int ni = 0; ni < 4; ++ni)
                mma_f16(acc[mi][ni], a[mi], (const uint32_t*)&bv[ni]);
    }
}

// ---------------- fused layer kernel ------------------------------------------
// GATHER=false, KDIM=128 : out = act(X @ W + b)
// GATHER=true,  KDIM=256 : out = act([X | max_j Htab16[idx[r][j]]] @ W + b)
// STATS : accumulate per-column sum / sumsq of the activation.
// PACKT : blocks >= NTILES pack the remaining weight matrices (wf1p/w2p/wf2p)
//         concurrently with the tile blocks (K1 only).
// MINB  : min blocks per SM (register budget: 4 needs <=64 regs — K=128 only)
template<int KDIM, bool RELU, bool GATHER, bool STATS, bool PACKT,
         bool FEAT16, bool WRITEF16, typename OUTT, int MINB>
__global__ void __launch_bounds__(256, MINB)
layer_kernel(const float*  __restrict__ Xf,     // fp32 features (FEAT16=false)
             const __half* __restrict__ Xh,     // fp16 features (FEAT16=true)
             const __half* __restrict__ Htab,
             const int*    __restrict__ nidx,
             const uint2*  __restrict__ Wp,
             const float*  __restrict__ bias,
             OUTT*   __restrict__ out,
             __half* __restrict__ f16out,
             float*  __restrict__ gsum,
             float*  __restrict__ gsq,
             const float* __restrict__ pf1,     // PACKT: fc1_W
             const float* __restrict__ pw2,     // PACKT: agg2_W
             const float* __restrict__ pf2)     // PACKT: fc2_W
{
    if (PACKT && blockIdx.x >= NTILES) {
        int b = blockIdx.x - NTILES;             // 0..39
        if      (b < 16) pack_mat(pf1, g_wf1p, b);
        else if (b < 24) pack_mat(pw2, g_w2p,  b - 16);
        else             pack_mat(pf2, g_wf2p, b - 24);
        return;
    }

    extern __shared__ __half sm[];
    constexpr int KPADH = KDIM + 8;
    __half* As  = sm;                             // MT * KPADH halfs
    float*  Sst = (float*)(sm + MT * KPADH);      // 256 floats (STATS)

    const int tid  = threadIdx.x;
    const int lane = tid & 31, wrp = tid >> 5;
    const int gid  = lane >> 2, tig = lane & 3;
    const int wm   = wrp >> 2,  wn  = wrp & 3;
    const int m0   = blockIdx.x * MT;

    if (STATS) Sst[tid] = 0.f;

    // ---- Phase A: stage A tile (features + optional fp16 gather-max) ----
#pragma unroll
    for (int q = 0; q < MT / 8; ++q) {
        int lr = wrp * (MT / 8) + q;
        int r  = m0 + lr; if (r >= NN) r = NN - 1;   // clamp (dup rows benign)

        if (FEAT16) {
            uint2 v = *(const uint2*)(Xh + (size_t)r * DH + lane * 4);
            *(uint2*)(As + lr * KPADH + lane * 4) = v;
        } else {
            float4 f = *(const float4*)(Xf + (size_t)r * DH + lane * 4);
            __half2 h0 = __floats2half2_rn(f.x, f.y);
            __half2 h1 = __floats2half2_rn(f.z, f.w);
            uint2 v;
            v.x = *(uint32_t*)&h0; v.y = *(uint32_t*)&h1;
            *(uint2*)(As + lr * KPADH + lane * 4) = v;
            if (WRITEF16)
                *(uint2*)(f16out + (size_t)r * DH + lane * 4) = v;
        }

        if (GATHER) {
            // half-warp scheme: lanes 0-15 take neighbors 0..12,
            // lanes 16-31 take 12..24 (j=12 duplicated; max idempotent).
            const int c  = lane & 15, hw = lane >> 4;
            const int* nb = nidx + r * S_NEI + hw * 12;
            __half2 mx0 = __float2half2_rn(0.f);   // post-relu values >= 0
            __half2 mx1 = mx0, mx2 = mx0, mx3 = mx0;
#pragma unroll
            for (int t = 0; t < 13; ++t) {
                int id = __ldg(nb + t);
                uint4 v = *(const uint4*)(Htab + (size_t)id * DH + c * 8);
                mx0 = __hmax2(mx0, *(__half2*)&v.x);
                mx1 = __hmax2(mx1, *(__half2*)&v.y);
                mx2 = __hmax2(mx2, *(__half2*)&v.z);
                mx3 = __hmax2(mx3, *(__half2*)&v.w);
            }
            uint4 o;
            uint32_t* mo = (uint32_t*)&o;
            __half2 mx[4] = {mx0, mx1, mx2, mx3};
#pragma unroll
            for (int i = 0; i < 4; ++i) {
                uint32_t mm = *(uint32_t*)&mx[i];
                uint32_t ot = __shfl_xor_sync(0xffffffffu, mm, 16);
                __half2 rr  = __hmax2(*(__half2*)&mm, *(__half2*)&ot);
                mo[i] = *(uint32_t*)&rr;
            }
            if (hw == 0)
                *(uint4*)(As + lr * KPADH + DH + c * 8) = o;
        }
    }

    float2 bb[4];
#pragma unroll
    for (int ni = 0; ni < 4; ++ni)
        bb[ni] = *(const float2*)(bias + wn * 32 + ni * 8 + 2 * tig);

    float acc[2][4][4];
#pragma unroll
    for (int mi = 0; mi < 2; ++mi)
#pragma unroll
        for (int ni = 0; ni < 4; ++ni)
#pragma unroll
            for (int c = 0; c < 4; ++c) acc[mi][ni][c] = 0.f;

    gemm_f16<KDIM>(As, Wp, tid, acc);

    // ---- Epilogue ----
    float ps[8], pq[8];
    if (STATS) {
#pragma unroll
        for (int j = 0; j < 8; ++j) { ps[j] = 0.f; pq[j] = 0.f; }
    }
#pragma unroll
    for (int mi = 0; mi < 2; ++mi) {
#pragma unroll
        for (int h = 0; h < 2; ++h) {
            int r = m0 + wm * 32 + mi * 16 + h * 8 + gid;
            if (r < NN) {
#pragma unroll
                for (int ni = 0; ni < 4; ++ni) {
                    float x0 = acc[mi][ni][h * 2 + 0] + bb[ni].x;
                    float x1 = acc[mi][ni][h * 2 + 1] + bb[ni].y;
                    if (RELU) { x0 = fmaxf(x0, 0.f); x1 = fmaxf(x1, 0.f); }
                    if (STATS) {
                        ps[ni * 2]     += x0; pq[ni * 2]     += x0 * x0;
                        ps[ni * 2 + 1] += x1; pq[ni * 2 + 1] += x1 * x1;
                    }
                    store2(out + (size_t)r * DH + wn * 32 + ni * 8 + 2 * tig,
                           x0, x1);
                }
            }
        }
    }

    if (STATS) {
        // reduce over gid (lanes 4 apart share tig)
#pragma unroll
        for (int j = 0; j < 8; ++j) {
#pragma unroll
            for (int o = 16; o >= 4; o >>= 1) {
                ps[j] += __shfl_xor_sync(0xffffffffu, ps[j], o);
                pq[j] += __shfl_xor_sync(0xffffffffu, pq[j], o);
            }
        }
        if (gid == 0) {
#pragma unroll
            for (int ni = 0; ni < 4; ++ni) {
                int c = wn * 32 + ni * 8 + 2 * tig;
                atomicAdd(Sst + c,           ps[ni * 2]);
                atomicAdd(Sst + c + 1,       ps[ni * 2 + 1]);
                atomicAdd(Sst + 128 + c,     pq[ni * 2]);
                atomicAdd(Sst + 128 + c + 1, pq[ni * 2 + 1]);
            }
        }
        __syncthreads();
        if (tid < DH) {
            atomicAdd(gsum + tid, Sst[tid]);
            atomicAdd(gsq + tid,  Sst[128 + tid]);
        }
    }
}

// ---------------- BN(inline finalize) + row-norm + GEMM -----------------------
__global__ void __launch_bounds__(256, 4)
bn_rownorm_gemm_kernel(const __half* __restrict__ X1,
                       const float* __restrict__ gsum,
                       const float* __restrict__ gsq,
                       const float* __restrict__ gamma,
                       const float* __restrict__ beta,
                       const uint2* __restrict__ Wp,
                       const float* __restrict__ bias,
                       __half* __restrict__ xn,
                       __half* __restrict__ h2)
{
    extern __shared__ __half sm[];
    constexpr int KPADH = DH + 8;
    __half* As = sm;

    const int tid  = threadIdx.x;
    const int lane = tid & 31, wrp = tid >> 5;
    const int gid  = lane >> 2, tig = tid & 3;
    const int wm   = wrp >> 2,  wn  = wrp & 3;
    const int m0   = blockIdx.x * MT;

    // inline BN finalize for this lane's 4 channels
    float sc[4], sh[4];
    {
        const float invN = 1.f / (float)NN;
#pragma unroll
        for (int i = 0; i < 4; ++i) {
            int c = lane * 4 + i;
            float mean = __ldg(gsum + c) * invN;
            float var  = __ldg(gsq + c) * invN - mean * mean;
            float s    = rsqrtf(var + 1e-5f) * __ldg(gamma + c);
            sc[i] = s;
            sh[i] = __ldg(beta + c) - mean * s;
        }
    }

    // batched row loads: all 8 LDGs in flight before any processing (MLP=8)
    uint2 raw[MT / 8];
#pragma unroll
    for (int q = 0; q < MT / 8; ++q) {
        int r = m0 + wrp * (MT / 8) + q; if (r >= NN) r = NN - 1;
        raw[q] = *(const uint2*)(X1 + (size_t)r * DH + lane * 4);
    }

#pragma unroll
    for (int q = 0; q < MT / 8; ++q) {
        int lr = wrp * (MT / 8) + q;
        int r  = m0 + lr; if (r >= NN) r = NN - 1;
        float2 f0 = __half22float2(*(__half2*)&raw[q].x);
        float2 f1 = __half22float2(*(__half2*)&raw[q].y);
        float v0 = fmaf(f0.x, sc[0], sh[0]);
        float v1 = fmaf(f0.y, sc[1], sh[1]);
        float v2 = fmaf(f1.x, sc[2], sh[2]);
        float v3 = fmaf(f1.y, sc[3], sh[3]);
        float ss = v0 * v0 + v1 * v1 + v2 * v2 + v3 * v3;
#pragma unroll
        for (int o = 16; o; o >>= 1) ss += __shfl_xor_sync(0xffffffffu, ss, o);
        float inv = 1.f / (sqrtf(ss) + 1e-6f);
        v0 *= inv; v1 *= inv; v2 *= inv; v3 *= inv;
        __half2 h0 = __floats2half2_rn(v0, v1);
        __half2 h1 = __floats2half2_rn(v2, v3);
        uint2 v;
        v.x = *(uint32_t*)&h0; v.y = *(uint32_t*)&h1;
        *(uint2*)(As + lr * KPADH + lane * 4) = v;
        *(uint2*)(xn + (size_t)r * DH + lane * 4) = v;  // dup rows same value
    }

    float2 bb[4];
#pragma unroll
    for (int ni = 0; ni < 4; ++ni)
        bb[ni] = *(const float2*)(bias + wn * 32 + ni * 8 + 2 * tig);

    float acc[2][4][4];
#pragma unroll
    for (int mi = 0; mi < 2; ++mi)
#pragma unroll
        for (int ni = 0; ni < 4; ++ni)
#pragma unroll
            for (int c = 0; c < 4; ++c) acc[mi][ni][c] = 0.f;

    gemm_f16<DH>(As, Wp, tid, acc);

#pragma unroll
    for (int mi = 0; mi < 2; ++mi) {
#pragma unroll
        for (int h = 0; h < 2; ++h) {
            int r = m0 + wm * 32 + mi * 16 + h * 8 + gid;
            if (r < NN) {
#pragma unroll
                for (int ni = 0; ni < 4; ++ni) {
                    float x0 = fmaxf(acc[mi][ni][h * 2 + 0] + bb[ni].x, 0.f);
                    float x1 = fmaxf(acc[mi][ni][h * 2 + 1] + bb[ni].y, 0.f);
                    store2(h2 + (size_t)r * DH + wn * 32 + ni * 8 + 2 * tig,
                           x0, x1);
                }
            }
        }
    }
}

// ---------------- host launch --------------------------------------------------
extern "C" void kernel_launch(void* const* d_in, const int* in_sizes, int n_in,
                              void* d_out, int out_size)
{
    const float* features = (const float*)d_in[0];
    const int*   idx1     = (const int*)  d_in[1];
    const int*   idx2     = (const int*)  d_in[2];
    const float* agg1_W   = (const float*)d_in[3];
    const float* agg1_b   = (const float*)d_in[4];
    const float* fc1_W    = (const float*)d_in[5];
    const float* fc1_b    = (const float*)d_in[6];
    const float* agg2_W   = (const float*)d_in[7];
    const float* agg2_b   = (const float*)d_in[8];
    const float* fc2_W    = (const float*)d_in[9];
    const float* fc2_b    = (const float*)d_in[10];
    const float* gamma    = (const float*)d_in[11];
    const float* beta     = (const float*)d_in[12];
    float* out = (float*)d_out;

    void *h1, *f16, *x1, *xn, *h2, *gsum, *gsq;
    void *w1p, *wf1p, *w2p, *wf2p;
    cudaGetSymbolAddress(&h1,   g_h1);
    cudaGetSymbolAddress(&f16,  g_f16);
    cudaGetSymbolAddress(&x1,   g_x1);
    cudaGetSymbolAddress(&xn,   g_xn);
    cudaGetSymbolAddress(&h2,   g_h2);
    cudaGetSymbolAddress(&gsum, g_sum);
    cudaGetSymbolAddress(&gsq,  g_sq);
    cudaGetSymbolAddress(&w1p,  g_w1p);
    cudaGetSymbolAddress(&wf1p, g_wf1p);
    cudaGetSymbolAddress(&w2p,  g_w2p);
    cudaGetSymbolAddress(&wf2p, g_wf2p);

    const int sm128  = MT * (128 + 8) * 2;                 // 17408 B
    const int sm256  = MT * (256 + 8) * 2;                 // 33792 B
    const int sm256s = sm256 + 256 * (int)sizeof(float);   // 34816 B

    cudaFuncSetAttribute(
        (const void*)layer_kernel<128, true, false, false, true, false, true, __half, 4>,
        cudaFuncAttributeMaxDynamicSharedMemorySize, sm128);
    cudaFuncSetAttribute(
        (const void*)layer_kernel<256, true, true, true, false, true, false, __half, 3>,
        cudaFuncAttributeMaxDynamicSharedMemorySize, sm256s);
    cudaFuncSetAttribute(
        (const void*)layer_kernel<256, false, true, false, false, true, false, float, 3>,
        cudaFuncAttributeMaxDynamicSharedMemorySize, sm256);
    cudaFuncSetAttribute((const void*)bn_rownorm_gemm_kernel,
        cudaFuncAttributeMaxDynamicSharedMemorySize, sm128);

    // K0: pack w1p (needed by K1) + zero BN stats — tiny (8 blocks)
    prep1_kernel<<<8, 256>>>(agg1_W, (float*)gsum, (float*)gsq);

    // K1: h1 = relu(F @ W1 + b) -> fp16; emits fp16 features.
    //     Extra 40 blocks pack wf1p/w2p/wf2p concurrently (ready before K2).
    layer_kernel<128, true, false, false, true, false, true, __half, 4>
        <<<NTILES + 40, 256, sm128>>>(
        features, nullptr, nullptr, nullptr, (const uint2*)w1p, agg1_b,
        (__half*)h1, (__half*)f16, (float*)gsum, (float*)gsq,
        fc1_W, agg2_W, fc2_W);

    // K2: x1 = relu([F16 | max h1[idx1]] @ Wf1 + b) -> fp16; BN stats
    layer_kernel<256, true, true, true, false, true, false, __half, 3>
        <<<NTILES, 256, sm256s>>>(
        nullptr, (const __half*)f16, (const __half*)h1, idx1,
        (const uint2*)wf1p, fc1_b, (__half*)x1, nullptr,
        (float*)gsum, (float*)gsq, nullptr, nullptr, nullptr);

    // K3: xn = rownorm(BN(x1)) -> fp16; h2 = relu(xn @ W2 + b) -> fp16
    bn_rownorm_gemm_kernel<<<NTILES, 256, sm128>>>(
        (const __half*)x1, (const float*)gsum, (const float*)gsq, gamma, beta,
        (const uint2*)w2p, agg2_b, (__half*)xn, (__half*)h2);

    // K4: out = [xn | max h2[idx2]] @ Wf2 + b  (fp32 output), occ 3 (no spill)
    layer_kernel<256, false, true, false, false, true, false, float, 3>
        <<<NTILES, 256, sm256>>>(
        nullptr, (const __half*)xn, (const __half*)h2, idx2,
        (const uint2*)wf2p, fc2_b, out, nullptr, nullptr, nullptr,
        nullptr, nullptr, nullptr);
}